// round 1
// baseline (speedup 1.0000x reference)
#include <cuda_runtime.h>
#include <math.h>

#define CB 2
#define CS 2048
#define CD 2048
#define CH 16
#define CHD 128
#define CM (CB*CS)          // 4096 rows total
#define SCALE 0.08838834764831845f   // 1/sqrt(128)

// Scratch (allocation-free rule: static device globals)
__device__ float g_q[(size_t)CM * CD];
__device__ float g_k[(size_t)CM * CD];
__device__ float g_v[(size_t)CM * CD];
__device__ float g_ao[(size_t)CM * CD];

// ---------------------------------------------------------------------------
// NT SGEMM: C[M,N] = A[M,K] * B[N,K]^T   (Linear: x @ W.T)
// 128x128x8 tile, 256 threads, 8x8 per-thread micro-tile.
// ---------------------------------------------------------------------------
__global__ __launch_bounds__(256) void sgemm_nt(
    const float* __restrict__ A, const float* __restrict__ Bm,
    float* __restrict__ C, int N, int K)
{
    __shared__ float As[8][132];
    __shared__ float Bs[8][132];

    const int tid = threadIdx.x;
    const int tx = tid & 15;
    const int ty = tid >> 4;
    const int bm = blockIdx.y << 7;
    const int bn = blockIdx.x << 7;

    const int lrow = tid >> 1;          // 0..127
    const int lk   = (tid & 1) << 2;    // 0 or 4

    const float* Ap = A  + (size_t)(bm + lrow) * K + lk;
    const float* Bp = Bm + (size_t)(bn + lrow) * K + lk;

    float acc[8][8];
#pragma unroll
    for (int i = 0; i < 8; i++)
#pragma unroll
        for (int j = 0; j < 8; j++) acc[i][j] = 0.f;

    for (int k0 = 0; k0 < K; k0 += 8) {
        float4 av = *(const float4*)(Ap + k0);
        float4 bv = *(const float4*)(Bp + k0);
        __syncthreads();
        As[lk + 0][lrow] = av.x; As[lk + 1][lrow] = av.y;
        As[lk + 2][lrow] = av.z; As[lk + 3][lrow] = av.w;
        Bs[lk + 0][lrow] = bv.x; Bs[lk + 1][lrow] = bv.y;
        Bs[lk + 2][lrow] = bv.z; Bs[lk + 3][lrow] = bv.w;
        __syncthreads();
#pragma unroll
        for (int kk = 0; kk < 8; kk++) {
            float a[8], bb[8];
            *(float4*)(a)      = *(const float4*)(&As[kk][ty << 3]);
            *(float4*)(a + 4)  = *(const float4*)(&As[kk][(ty << 3) + 4]);
            *(float4*)(bb)     = *(const float4*)(&Bs[kk][tx << 3]);
            *(float4*)(bb + 4) = *(const float4*)(&Bs[kk][(tx << 3) + 4]);
#pragma unroll
            for (int i = 0; i < 8; i++)
#pragma unroll
                for (int j = 0; j < 8; j++)
                    acc[i][j] = fmaf(a[i], bb[j], acc[i][j]);
        }
    }

#pragma unroll
    for (int i = 0; i < 8; i++) {
        float* Cp = C + (size_t)(bm + (ty << 3) + i) * N + bn + (tx << 3);
        float4 o0 = make_float4(acc[i][0], acc[i][1], acc[i][2], acc[i][3]);
        float4 o1 = make_float4(acc[i][4], acc[i][5], acc[i][6], acc[i][7]);
        *(float4*)(Cp)     = o0;
        *(float4*)(Cp + 4) = o1;
    }
}

// ---------------------------------------------------------------------------
// RoPE applied in place to g_q and g_k.
// One thread per (row m, head h, half-dim i<64) pair.
// ---------------------------------------------------------------------------
__global__ __launch_bounds__(256) void rope_kernel()
{
    int idx = blockIdx.x * 256 + threadIdx.x;   // exact: CM*CH*64 threads
    int i = idx & 63;
    int h = (idx >> 6) & (CH - 1);
    int m = idx >> 10;                          // 64*16 = 1024
    int s = m & (CS - 1);

    // inv_freq[i] = 1/10000^(2i/128); double pow rounded to fp32 (matches jnp
    // fp32 value to <=1 ulp), fp32 angle, fp32 trig -> mimics reference path.
    float inv = (float)(1.0 / pow(10000.0, (double)(2 * i) / (double)CHD));
    float ang = (float)s * inv;
    float c, sn;
    __sincosf(ang, &sn, &c);
    // use accurate versions (sincosf-fast has 2^-21 err; fine, but accurate is cheap here)
    c = cosf(ang); sn = sinf(ang);

    size_t base = (size_t)m * CD + (size_t)h * CHD;
    float q1 = g_q[base + i], q2 = g_q[base + i + 64];
    g_q[base + i]      = q1 * c - q2 * sn;
    g_q[base + i + 64] = q2 * c + q1 * sn;
    float k1 = g_k[base + i], k2 = g_k[base + i + 64];
    g_k[base + i]      = k1 * c - k2 * sn;
    g_k[base + i + 64] = k2 * c + k1 * sn;
}

// ---------------------------------------------------------------------------
// Flash attention: one CTA per (q-tile 128, head, batch).
// Q kept transposed in smem, K/V share one buffer, S tile 128x128, online
// softmax, fp32 throughout.
// smem: Q_t[128][132] + KV[128][132] + S[128][132] + stats -> 204288 B
// ---------------------------------------------------------------------------
#define TPAD 132
#define FLASH_SMEM ((3 * 128 * TPAD + 3 * 128) * sizeof(float))

__global__ __launch_bounds__(256) void flash_attn(const float* __restrict__ mask)
{
    extern __shared__ float sm[];
    float* Qs  = sm;                       // [dd][ql]  (transposed)
    float* KVs = sm + 128 * TPAD;          // K: [dd][kl] ; V: [kl][dd]
    float* Ss  = sm + 2 * 128 * TPAD;      // [r][c]
    float* m_s  = sm + 3 * 128 * TPAD;
    float* l_s  = m_s + 128;
    float* al_s = l_s + 128;

    const int tid = threadIdx.x;
    const int tx = tid & 15;
    const int ty = tid >> 4;
    const int b  = blockIdx.z;
    const int h  = blockIdx.y;
    const int q0 = blockIdx.x << 7;

    const float* Qg = g_q + ((size_t)(b * CS + q0)) * CD + (size_t)h * CHD;
    const float* Kg = g_k + ((size_t)b * CS) * CD + (size_t)h * CHD;
    const float* Vg = g_v + ((size_t)b * CS) * CD + (size_t)h * CHD;

    // load Q tile transposed: Qs[dd][ql]
    for (int idx = tid * 4; idx < 128 * 128; idx += 1024) {
        int ql = idx >> 7;
        int dd = idx & 127;
        float4 v = *(const float4*)(Qg + (size_t)ql * CD + dd);
        Qs[(dd + 0) * TPAD + ql] = v.x;
        Qs[(dd + 1) * TPAD + ql] = v.y;
        Qs[(dd + 2) * TPAD + ql] = v.z;
        Qs[(dd + 3) * TPAD + ql] = v.w;
    }
    if (tid < 128) { m_s[tid] = -INFINITY; l_s[tid] = 0.f; }

    float acc[8][8];
#pragma unroll
    for (int i = 0; i < 8; i++)
#pragma unroll
        for (int j = 0; j < 8; j++) acc[i][j] = 0.f;

    for (int kt = 0; kt < CS / 128; kt++) {
        const int k0 = kt << 7;
        __syncthreads();   // protect KVs/Ss reuse from previous iteration
        // load K transposed: KVs[dd][kl]
        for (int idx = tid * 4; idx < 128 * 128; idx += 1024) {
            int kl = idx >> 7;
            int dd = idx & 127;
            float4 v = *(const float4*)(Kg + (size_t)(k0 + kl) * CD + dd);
            KVs[(dd + 0) * TPAD + kl] = v.x;
            KVs[(dd + 1) * TPAD + kl] = v.y;
            KVs[(dd + 2) * TPAD + kl] = v.z;
            KVs[(dd + 3) * TPAD + kl] = v.w;
        }
        __syncthreads();

        // S = Q * K^T  (8x8 per thread)
        float sacc[8][8];
#pragma unroll
        for (int i = 0; i < 8; i++)
#pragma unroll
            for (int j = 0; j < 8; j++) sacc[i][j] = 0.f;

#pragma unroll 4
        for (int dd = 0; dd < 128; dd++) {
            float a[8], bb[8];
            *(float4*)(a)      = *(const float4*)(&Qs[dd * TPAD + (ty << 3)]);
            *(float4*)(a + 4)  = *(const float4*)(&Qs[dd * TPAD + (ty << 3) + 4]);
            *(float4*)(bb)     = *(const float4*)(&KVs[dd * TPAD + (tx << 3)]);
            *(float4*)(bb + 4) = *(const float4*)(&KVs[dd * TPAD + (tx << 3) + 4]);
#pragma unroll
            for (int i = 0; i < 8; i++)
#pragma unroll
                for (int j = 0; j < 8; j++)
                    sacc[i][j] = fmaf(a[i], bb[j], sacc[i][j]);
        }
#pragma unroll
        for (int i = 0; i < 8; i++) {
            float* sp = &Ss[((ty << 3) + i) * TPAD + (tx << 3)];
            *(float4*)(sp)     = make_float4(sacc[i][0], sacc[i][1], sacc[i][2], sacc[i][3]);
            *(float4*)(sp + 4) = make_float4(sacc[i][4], sacc[i][5], sacc[i][6], sacc[i][7]);
        }
        __syncthreads();   // Ss complete; K reads done -> KVs free for V

        // load V natural: KVs[kl][dd]
        for (int idx = tid * 4; idx < 128 * 128; idx += 1024) {
            int kl = idx >> 7;
            int dd = idx & 127;
            float4 v = *(const float4*)(Vg + (size_t)(k0 + kl) * CD + dd);
            *(float4*)(&KVs[kl * TPAD + dd]) = v;
        }

        // online softmax: one thread per row
        if (tid < 128) {
            const int r = tid;
            const float* mrow = mask + ((size_t)b * CS + (q0 + r)) * CS + k0;
            float mx = m_s[r];
            float* srow = &Ss[r * TPAD];
#pragma unroll 4
            for (int c4 = 0; c4 < 32; c4++) {
                float4 mv = *(const float4*)(mrow + c4 * 4);
                float4 sv = *(float4*)(srow + c4 * 4);
                sv.x = sv.x * SCALE + mv.x;
                sv.y = sv.y * SCALE + mv.y;
                sv.z = sv.z * SCALE + mv.z;
                sv.w = sv.w * SCALE + mv.w;
                *(float4*)(srow + c4 * 4) = sv;
                mx = fmaxf(mx, fmaxf(fmaxf(sv.x, sv.y), fmaxf(sv.z, sv.w)));
            }
            float al = __expf(m_s[r] - mx);
            float sum = 0.f;
#pragma unroll 4
            for (int c4 = 0; c4 < 32; c4++) {
                float4 sv = *(float4*)(srow + c4 * 4);
                sv.x = __expf(sv.x - mx);
                sv.y = __expf(sv.y - mx);
                sv.z = __expf(sv.z - mx);
                sv.w = __expf(sv.w - mx);
                *(float4*)(srow + c4 * 4) = sv;
                sum += sv.x + sv.y + sv.z + sv.w;
            }
            m_s[r]  = mx;
            l_s[r]  = l_s[r] * al + sum;
            al_s[r] = al;
        }
        __syncthreads();

        // rescale accumulator, then O += P * V
#pragma unroll
        for (int i = 0; i < 8; i++) {
            float al = al_s[(ty << 3) + i];
#pragma unroll
            for (int j = 0; j < 8; j++) acc[i][j] *= al;
        }
#pragma unroll 2
        for (int kk = 0; kk < 128; kk++) {
            float bb[8];
            *(float4*)(bb)     = *(const float4*)(&KVs[kk * TPAD + (tx << 3)]);
            *(float4*)(bb + 4) = *(const float4*)(&KVs[kk * TPAD + (tx << 3) + 4]);
#pragma unroll
            for (int i = 0; i < 8; i++) {
                float p = Ss[((ty << 3) + i) * TPAD + kk];
#pragma unroll
                for (int j = 0; j < 8; j++)
                    acc[i][j] = fmaf(p, bb[j], acc[i][j]);
            }
        }
    }

    // epilogue: divide by l, write to g_ao in [B,S,D] layout
    float* Og = g_ao + ((size_t)(b * CS + q0)) * CD + (size_t)h * CHD;
#pragma unroll
    for (int i = 0; i < 8; i++) {
        float inv = 1.0f / l_s[(ty << 3) + i];
        float* op = Og + (size_t)((ty << 3) + i) * CD + (tx << 3);
        *(float4*)(op)     = make_float4(acc[i][0] * inv, acc[i][1] * inv,
                                         acc[i][2] * inv, acc[i][3] * inv);
        *(float4*)(op + 4) = make_float4(acc[i][4] * inv, acc[i][5] * inv,
                                         acc[i][6] * inv, acc[i][7] * inv);
    }
}

// ---------------------------------------------------------------------------
extern "C" void kernel_launch(void* const* d_in, const int* in_sizes, int n_in,
                              void* d_out, int out_size)
{
    const float* X    = (const float*)d_in[0];
    const float* mask = (const float*)d_in[1];
    const float* Wq   = (const float*)d_in[2];
    const float* Wk   = (const float*)d_in[3];
    const float* Wv   = (const float*)d_in[4];
    const float* Wo   = (const float*)d_in[5];
    float* out = (float*)d_out;

    float *qp, *kp, *vp, *aop;
    cudaGetSymbolAddress((void**)&qp,  g_q);
    cudaGetSymbolAddress((void**)&kp,  g_k);
    cudaGetSymbolAddress((void**)&vp,  g_v);
    cudaGetSymbolAddress((void**)&aop, g_ao);

    cudaFuncSetAttribute(flash_attn, cudaFuncAttributeMaxDynamicSharedMemorySize,
                         (int)FLASH_SMEM);

    dim3 gg(CD / 128, CM / 128);   // (16, 32)
    sgemm_nt<<<gg, 256>>>(X, Wq, qp, CD, CD);
    sgemm_nt<<<gg, 256>>>(X, Wk, kp, CD, CD);
    sgemm_nt<<<gg, 256>>>(X, Wv, vp, CD, CD);

    rope_kernel<<<(CM * CH * 64) / 256, 256>>>();

    flash_attn<<<dim3(CS / 128, CH, CB), 256, FLASH_SMEM>>>(mask);

    sgemm_nt<<<gg, 256>>>(aop, Wo, out, CD, CD);
}

// round 2
// speedup vs baseline: 1.1620x; 1.1620x over previous
#include <cuda_runtime.h>
#include <math.h>

#define CB 2
#define CS 2048
#define CD 2048
#define CH 16
#define CHD 128
#define CM (CB*CS)          // 4096 rows total
#define SCALE 0.08838834764831845f   // 1/sqrt(128)

// Scratch (allocation-free rule: static device globals)
__device__ float g_q[(size_t)CM * CD];
__device__ float g_k[(size_t)CM * CD];
__device__ float g_v[(size_t)CM * CD];
__device__ float g_ao[(size_t)CM * CD];
__device__ float g_invf[64];

// ---------------------------------------------------------------------------
// Precompute RoPE inverse frequencies with double pow (64 values total).
// ---------------------------------------------------------------------------
__global__ void init_invf()
{
    int i = threadIdx.x;
    if (i < 64)
        g_invf[i] = (float)(1.0 / pow(10000.0, (double)(2 * i) / (double)CHD));
}

// ---------------------------------------------------------------------------
// NT SGEMM: C[M,N] = A[M,K] * B[N,K]^T   (Linear: x @ W.T)
// 128x128x8 tile, 256 threads, 8x8 per-thread micro-tile.
// Double-buffered smem + register-staged global loads; one sync per k-step.
// blockIdx.z selects among up to 3 (B, C) pairs (fused Q/K/V projections).
// ---------------------------------------------------------------------------
__global__ __launch_bounds__(256, 2) void sgemm_nt(
    const float* __restrict__ A,
    const float* __restrict__ B0, const float* __restrict__ B1,
    const float* __restrict__ B2,
    float* __restrict__ C0, float* __restrict__ C1, float* __restrict__ C2,
    int N, int K)
{
    __shared__ float As[2][8][132];
    __shared__ float Bs[2][8][132];

    const float* Bm = (blockIdx.z == 0) ? B0 : (blockIdx.z == 1) ? B1 : B2;
    float*       C  = (blockIdx.z == 0) ? C0 : (blockIdx.z == 1) ? C1 : C2;

    const int tid = threadIdx.x;
    const int tx = tid & 15;
    const int ty = tid >> 4;
    const int bm = blockIdx.y << 7;
    const int bn = blockIdx.x << 7;

    const int lrow = tid >> 1;          // 0..127
    const int lk   = (tid & 1) << 2;    // 0 or 4

    const float* Ap = A  + (size_t)(bm + lrow) * K + lk;
    const float* Bp = Bm + (size_t)(bn + lrow) * K + lk;

    float acc[8][8];
#pragma unroll
    for (int i = 0; i < 8; i++)
#pragma unroll
        for (int j = 0; j < 8; j++) acc[i][j] = 0.f;

    // prologue: fill buffer 0
    {
        float4 av = *(const float4*)(Ap);
        float4 bv = *(const float4*)(Bp);
        As[0][lk + 0][lrow] = av.x; As[0][lk + 1][lrow] = av.y;
        As[0][lk + 2][lrow] = av.z; As[0][lk + 3][lrow] = av.w;
        Bs[0][lk + 0][lrow] = bv.x; Bs[0][lk + 1][lrow] = bv.y;
        Bs[0][lk + 2][lrow] = bv.z; Bs[0][lk + 3][lrow] = bv.w;
    }
    __syncthreads();

    for (int k0 = 0; k0 < K; k0 += 8) {
        const int cur = (k0 >> 3) & 1;
        const int nxt = cur ^ 1;
        const bool more = (k0 + 8) < K;

        float4 av, bv;
        if (more) {
            av = *(const float4*)(Ap + k0 + 8);
            bv = *(const float4*)(Bp + k0 + 8);
        }

#pragma unroll
        for (int kk = 0; kk < 8; kk++) {
            float a[8], bb[8];
            *(float4*)(a)      = *(const float4*)(&As[cur][kk][ty << 3]);
            *(float4*)(a + 4)  = *(const float4*)(&As[cur][kk][(ty << 3) + 4]);
            *(float4*)(bb)     = *(const float4*)(&Bs[cur][kk][tx << 3]);
            *(float4*)(bb + 4) = *(const float4*)(&Bs[cur][kk][(tx << 3) + 4]);
#pragma unroll
            for (int i = 0; i < 8; i++)
#pragma unroll
                for (int j = 0; j < 8; j++)
                    acc[i][j] = fmaf(a[i], bb[j], acc[i][j]);
        }

        if (more) {
            As[nxt][lk + 0][lrow] = av.x; As[nxt][lk + 1][lrow] = av.y;
            As[nxt][lk + 2][lrow] = av.z; As[nxt][lk + 3][lrow] = av.w;
            Bs[nxt][lk + 0][lrow] = bv.x; Bs[nxt][lk + 1][lrow] = bv.y;
            Bs[nxt][lk + 2][lrow] = bv.z; Bs[nxt][lk + 3][lrow] = bv.w;
        }
        __syncthreads();
    }

#pragma unroll
    for (int i = 0; i < 8; i++) {
        float* Cp = C + (size_t)(bm + (ty << 3) + i) * N + bn + (tx << 3);
        float4 o0 = make_float4(acc[i][0], acc[i][1], acc[i][2], acc[i][3]);
        float4 o1 = make_float4(acc[i][4], acc[i][5], acc[i][6], acc[i][7]);
        *(float4*)(Cp)     = o0;
        *(float4*)(Cp + 4) = o1;
    }
}

// ---------------------------------------------------------------------------
// RoPE applied in place to g_q and g_k, using precomputed inv_freq.
// One thread per (row m, head h, half-dim i<64) pair.
// ---------------------------------------------------------------------------
__global__ __launch_bounds__(256) void rope_kernel()
{
    int idx = blockIdx.x * 256 + threadIdx.x;   // exact: CM*CH*64 threads
    int i = idx & 63;
    int m = idx >> 10;                          // 64*16 = 1024
    int s = m & (CS - 1);

    float inv = g_invf[i];
    float ang = (float)s * inv;
    float c, sn;
    sincosf(ang, &sn, &c);   // accurate versions

    int h = (idx >> 6) & (CH - 1);
    size_t base = (size_t)m * CD + (size_t)h * CHD;
    float q1 = g_q[base + i], q2 = g_q[base + i + 64];
    g_q[base + i]      = q1 * c - q2 * sn;
    g_q[base + i + 64] = q2 * c + q1 * sn;
    float k1 = g_k[base + i], k2 = g_k[base + i + 64];
    g_k[base + i]      = k1 * c - k2 * sn;
    g_k[base + i + 64] = k2 * c + k1 * sn;
}

// ---------------------------------------------------------------------------
// Flash attention: one CTA per (q-tile 128, head, batch).
// Q kept transposed in smem, K/V share one buffer, S tile 128x128, online
// softmax (2 threads per row), fp32 throughout.
// smem: Q_t[128][132] + KV[128][132] + S[128][132] + stats -> 204288 B
// ---------------------------------------------------------------------------
#define TPAD 132
#define FLASH_SMEM ((3 * 128 * TPAD + 3 * 128) * sizeof(float))

__global__ __launch_bounds__(256) void flash_attn(const float* __restrict__ mask)
{
    extern __shared__ float sm[];
    float* Qs  = sm;                       // [dd][ql]  (transposed)
    float* KVs = sm + 128 * TPAD;          // K: [dd][kl] ; V: [kl][dd]
    float* Ss  = sm + 2 * 128 * TPAD;      // [r][c]
    float* m_s  = sm + 3 * 128 * TPAD;
    float* l_s  = m_s + 128;
    float* al_s = l_s + 128;

    const int tid = threadIdx.x;
    const int tx = tid & 15;
    const int ty = tid >> 4;
    const int b  = blockIdx.z;
    const int h  = blockIdx.y;
    const int q0 = blockIdx.x << 7;

    const float* Qg = g_q + ((size_t)(b * CS + q0)) * CD + (size_t)h * CHD;
    const float* Kg = g_k + ((size_t)b * CS) * CD + (size_t)h * CHD;
    const float* Vg = g_v + ((size_t)b * CS) * CD + (size_t)h * CHD;

    // load Q tile transposed: Qs[dd][ql]
    for (int idx = tid * 4; idx < 128 * 128; idx += 1024) {
        int ql = idx >> 7;
        int dd = idx & 127;
        float4 v = *(const float4*)(Qg + (size_t)ql * CD + dd);
        Qs[(dd + 0) * TPAD + ql] = v.x;
        Qs[(dd + 1) * TPAD + ql] = v.y;
        Qs[(dd + 2) * TPAD + ql] = v.z;
        Qs[(dd + 3) * TPAD + ql] = v.w;
    }
    if (tid < 128) { m_s[tid] = -INFINITY; l_s[tid] = 0.f; }

    float acc[8][8];
#pragma unroll
    for (int i = 0; i < 8; i++)
#pragma unroll
        for (int j = 0; j < 8; j++) acc[i][j] = 0.f;

    for (int kt = 0; kt < CS / 128; kt++) {
        const int k0 = kt << 7;
        __syncthreads();   // protect KVs/Ss reuse from previous iteration
        // load K transposed: KVs[dd][kl]
        for (int idx = tid * 4; idx < 128 * 128; idx += 1024) {
            int kl = idx >> 7;
            int dd = idx & 127;
            float4 v = *(const float4*)(Kg + (size_t)(k0 + kl) * CD + dd);
            KVs[(dd + 0) * TPAD + kl] = v.x;
            KVs[(dd + 1) * TPAD + kl] = v.y;
            KVs[(dd + 2) * TPAD + kl] = v.z;
            KVs[(dd + 3) * TPAD + kl] = v.w;
        }
        __syncthreads();

        // S = Q * K^T  (8x8 per thread)
        float sacc[8][8];
#pragma unroll
        for (int i = 0; i < 8; i++)
#pragma unroll
            for (int j = 0; j < 8; j++) sacc[i][j] = 0.f;

#pragma unroll 4
        for (int dd = 0; dd < 128; dd++) {
            float a[8], bb[8];
            *(float4*)(a)      = *(const float4*)(&Qs[dd * TPAD + (ty << 3)]);
            *(float4*)(a + 4)  = *(const float4*)(&Qs[dd * TPAD + (ty << 3) + 4]);
            *(float4*)(bb)     = *(const float4*)(&KVs[dd * TPAD + (tx << 3)]);
            *(float4*)(bb + 4) = *(const float4*)(&KVs[dd * TPAD + (tx << 3) + 4]);
#pragma unroll
            for (int i = 0; i < 8; i++)
#pragma unroll
                for (int j = 0; j < 8; j++)
                    sacc[i][j] = fmaf(a[i], bb[j], sacc[i][j]);
        }
#pragma unroll
        for (int i = 0; i < 8; i++) {
            float* sp = &Ss[((ty << 3) + i) * TPAD + (tx << 3)];
            *(float4*)(sp)     = make_float4(sacc[i][0], sacc[i][1], sacc[i][2], sacc[i][3]);
            *(float4*)(sp + 4) = make_float4(sacc[i][4], sacc[i][5], sacc[i][6], sacc[i][7]);
        }
        __syncthreads();   // Ss complete; K reads done -> KVs free for V

        // load V natural: KVs[kl][dd]
        for (int idx = tid * 4; idx < 128 * 128; idx += 1024) {
            int kl = idx >> 7;
            int dd = idx & 127;
            float4 v = *(const float4*)(Vg + (size_t)(k0 + kl) * CD + dd);
            *(float4*)(&KVs[kl * TPAD + dd]) = v;
        }

        // online softmax: 2 threads per row (adjacent lanes), 64 cols each
        {
            const int r  = tid >> 1;
            const int hf = tid & 1;
            const float* mrow = mask + ((size_t)b * CS + (q0 + r)) * CS + k0 + hf * 64;
            float* srow = &Ss[r * TPAD + hf * 64];
            float mprev = m_s[r];      // read by both lanes pre-divergence
            float lprev = l_s[r];

            float mx = -INFINITY;
#pragma unroll 4
            for (int c4 = 0; c4 < 16; c4++) {
                float4 mv = *(const float4*)(mrow + c4 * 4);
                float4 sv = *(float4*)(srow + c4 * 4);
                sv.x = sv.x * SCALE + mv.x;
                sv.y = sv.y * SCALE + mv.y;
                sv.z = sv.z * SCALE + mv.z;
                sv.w = sv.w * SCALE + mv.w;
                *(float4*)(srow + c4 * 4) = sv;
                mx = fmaxf(mx, fmaxf(fmaxf(sv.x, sv.y), fmaxf(sv.z, sv.w)));
            }
            mx = fmaxf(mx, __shfl_xor_sync(0xffffffffu, mx, 1));
            mx = fmaxf(mx, mprev);

            float sum = 0.f;
#pragma unroll 4
            for (int c4 = 0; c4 < 16; c4++) {
                float4 sv = *(float4*)(srow + c4 * 4);
                sv.x = __expf(sv.x - mx);
                sv.y = __expf(sv.y - mx);
                sv.z = __expf(sv.z - mx);
                sv.w = __expf(sv.w - mx);
                *(float4*)(srow + c4 * 4) = sv;
                sum += sv.x + sv.y + sv.z + sv.w;
            }
            sum += __shfl_xor_sync(0xffffffffu, sum, 1);

            if (hf == 0) {
                float al = __expf(mprev - mx);
                m_s[r]  = mx;
                l_s[r]  = lprev * al + sum;
                al_s[r] = al;
            }
        }
        __syncthreads();

        // rescale accumulator, then O += P * V
#pragma unroll
        for (int i = 0; i < 8; i++) {
            float al = al_s[(ty << 3) + i];
#pragma unroll
            for (int j = 0; j < 8; j++) acc[i][j] *= al;
        }
#pragma unroll 2
        for (int kk = 0; kk < 128; kk++) {
            float bb[8];
            *(float4*)(bb)     = *(const float4*)(&KVs[kk * TPAD + (tx << 3)]);
            *(float4*)(bb + 4) = *(const float4*)(&KVs[kk * TPAD + (tx << 3) + 4]);
#pragma unroll
            for (int i = 0; i < 8; i++) {
                float p = Ss[((ty << 3) + i) * TPAD + kk];
#pragma unroll
                for (int j = 0; j < 8; j++)
                    acc[i][j] = fmaf(p, bb[j], acc[i][j]);
            }
        }
    }

    // epilogue: divide by l, write to g_ao in [B,S,D] layout
    float* Og = g_ao + ((size_t)(b * CS + q0)) * CD + (size_t)h * CHD;
#pragma unroll
    for (int i = 0; i < 8; i++) {
        float inv = 1.0f / l_s[(ty << 3) + i];
        float* op = Og + (size_t)((ty << 3) + i) * CD + (tx << 3);
        *(float4*)(op)     = make_float4(acc[i][0] * inv, acc[i][1] * inv,
                                         acc[i][2] * inv, acc[i][3] * inv);
        *(float4*)(op + 4) = make_float4(acc[i][4] * inv, acc[i][5] * inv,
                                         acc[i][6] * inv, acc[i][7] * inv);
    }
}

// ---------------------------------------------------------------------------
extern "C" void kernel_launch(void* const* d_in, const int* in_sizes, int n_in,
                              void* d_out, int out_size)
{
    const float* X    = (const float*)d_in[0];
    const float* mask = (const float*)d_in[1];
    const float* Wq   = (const float*)d_in[2];
    const float* Wk   = (const float*)d_in[3];
    const float* Wv   = (const float*)d_in[4];
    const float* Wo   = (const float*)d_in[5];
    float* out = (float*)d_out;

    float *qp, *kp, *vp, *aop;
    cudaGetSymbolAddress((void**)&qp,  g_q);
    cudaGetSymbolAddress((void**)&kp,  g_k);
    cudaGetSymbolAddress((void**)&vp,  g_v);
    cudaGetSymbolAddress((void**)&aop, g_ao);

    cudaFuncSetAttribute(flash_attn, cudaFuncAttributeMaxDynamicSharedMemorySize,
                         (int)FLASH_SMEM);

    init_invf<<<1, 64>>>();

    // fused Q/K/V projections: blockIdx.z selects weight/output
    sgemm_nt<<<dim3(CD / 128, CM / 128, 3), 256>>>(X, Wq, Wk, Wv, qp, kp, vp, CD, CD);

    rope_kernel<<<(CM * CH * 64) / 256, 256>>>();

    flash_attn<<<dim3(CS / 128, CH, CB), 256, FLASH_SMEM>>>(mask);

    // O projection
    sgemm_nt<<<dim3(CD / 128, CM / 128, 1), 256>>>(aop, Wo, Wo, Wo, out, out, out, CD, CD);
}

// round 3
// speedup vs baseline: 1.8285x; 1.5736x over previous
#include <cuda_runtime.h>
#include <cuda_bf16.h>
#include <math.h>
#include <stdint.h>

#define CB 2
#define CS 2048
#define CD 2048
#define CH 16
#define CHD 128
#define CM (CB*CS)          // 4096 rows total
#define SCALE 0.08838834764831845f   // 1/sqrt(128)

// ---------------------------------------------------------------------------
// Scratch (allocation-free rule: static device globals)
// ---------------------------------------------------------------------------
__device__ float g_q[(size_t)CM * CD];
__device__ float g_k[(size_t)CM * CD];
__device__ float g_v[(size_t)CM * CD];
__device__ float g_invf[64];

__device__ __nv_bfloat16 g_xh[(size_t)CM * CD];
__device__ __nv_bfloat16 g_xl[(size_t)CM * CD];
__device__ __nv_bfloat16 g_wqh[(size_t)CD * CD];
__device__ __nv_bfloat16 g_wql[(size_t)CD * CD];
__device__ __nv_bfloat16 g_wkh[(size_t)CD * CD];
__device__ __nv_bfloat16 g_wkl[(size_t)CD * CD];
__device__ __nv_bfloat16 g_wvh[(size_t)CD * CD];
__device__ __nv_bfloat16 g_wvl[(size_t)CD * CD];
__device__ __nv_bfloat16 g_woh[(size_t)CD * CD];
__device__ __nv_bfloat16 g_wol[(size_t)CD * CD];
__device__ __nv_bfloat16 g_aoh[(size_t)CM * CD];
__device__ __nv_bfloat16 g_aol[(size_t)CM * CD];

// ---------------------------------------------------------------------------
// PTX helpers
// ---------------------------------------------------------------------------
__device__ __forceinline__ uint32_t smem_u32(const void* p) {
    return (uint32_t)__cvta_generic_to_shared(p);
}

__device__ __forceinline__ void ldsm4(uint32_t& r0, uint32_t& r1,
                                      uint32_t& r2, uint32_t& r3, uint32_t addr) {
    asm volatile("ldmatrix.sync.aligned.m8n8.x4.shared.b16 {%0,%1,%2,%3}, [%4];"
                 : "=r"(r0), "=r"(r1), "=r"(r2), "=r"(r3) : "r"(addr));
}

__device__ __forceinline__ void mma16816(float* c, const uint32_t* a, const uint32_t* b) {
    asm volatile(
        "mma.sync.aligned.m16n8k16.row.col.f32.bf16.bf16.f32 "
        "{%0,%1,%2,%3}, {%4,%5,%6,%7}, {%8,%9}, {%0,%1,%2,%3};"
        : "+f"(c[0]), "+f"(c[1]), "+f"(c[2]), "+f"(c[3])
        : "r"(a[0]), "r"(a[1]), "r"(a[2]), "r"(a[3]), "r"(b[0]), "r"(b[1]));
}

// ---------------------------------------------------------------------------
// Precompute RoPE inverse frequencies with double pow (64 values total).
// ---------------------------------------------------------------------------
__global__ void init_invf()
{
    int i = threadIdx.x;
    if (i < 64)
        g_invf[i] = (float)(1.0 / pow(10000.0, (double)(2 * i) / (double)CHD));
}

// ---------------------------------------------------------------------------
// fp32 -> (bf16 hi, bf16 lo) split conversion. 4 elements per thread.
// ---------------------------------------------------------------------------
__global__ __launch_bounds__(256) void convert_hilo(
    const float* __restrict__ src,
    __nv_bfloat16* __restrict__ hi, __nv_bfloat16* __restrict__ lo, int n4)
{
    int i = blockIdx.x * 256 + threadIdx.x;
    if (i >= n4) return;
    float4 v = ((const float4*)src)[i];
    __nv_bfloat16 h0 = __float2bfloat16_rn(v.x);
    __nv_bfloat16 h1 = __float2bfloat16_rn(v.y);
    __nv_bfloat16 h2 = __float2bfloat16_rn(v.z);
    __nv_bfloat16 h3 = __float2bfloat16_rn(v.w);
    __nv_bfloat16 l0 = __float2bfloat16_rn(v.x - __bfloat162float(h0));
    __nv_bfloat16 l1 = __float2bfloat16_rn(v.y - __bfloat162float(h1));
    __nv_bfloat16 l2 = __float2bfloat16_rn(v.z - __bfloat162float(h2));
    __nv_bfloat16 l3 = __float2bfloat16_rn(v.w - __bfloat162float(h3));
    ((__nv_bfloat162*)hi)[2 * i]     = __nv_bfloat162(h0, h1);
    ((__nv_bfloat162*)hi)[2 * i + 1] = __nv_bfloat162(h2, h3);
    ((__nv_bfloat162*)lo)[2 * i]     = __nv_bfloat162(l0, l1);
    ((__nv_bfloat162*)lo)[2 * i + 1] = __nv_bfloat162(l2, l3);
}

// ---------------------------------------------------------------------------
// bf16-split tensor-core NT GEMM: C[M,N] = A * B^T with A = Ah+Al, B = Bh+Bl.
// C = Ah Bh^T + Ah Bl^T + Al Bh^T  (fp32 accumulate).
// 128x128x32 CTA tile, 256 threads = 8 warps (2x4), warp tile 64x32.
// smem rows are 40 bf16 (80B) so ldmatrix phases hit distinct bank groups.
// blockIdx.z selects among up to 3 (B, C) pairs (fused Q/K/V projections).
// ---------------------------------------------------------------------------
#define TILE_ELEM (128 * 40)       // bf16 elements per smem tile (5120)
#define STAGE_ELEM (4 * TILE_ELEM) // Ah, Al, Bh, Bl
#define GEMM_SMEM (2 * STAGE_ELEM * 2)  // bytes (81920)

__global__ __launch_bounds__(256, 1) void gemm_bf16x3(
    const __nv_bfloat16* __restrict__ Ah, const __nv_bfloat16* __restrict__ Al,
    const __nv_bfloat16* __restrict__ Bh0, const __nv_bfloat16* __restrict__ Bl0,
    const __nv_bfloat16* __restrict__ Bh1, const __nv_bfloat16* __restrict__ Bl1,
    const __nv_bfloat16* __restrict__ Bh2, const __nv_bfloat16* __restrict__ Bl2,
    float* __restrict__ C0, float* __restrict__ C1, float* __restrict__ C2,
    int N, int K)
{
    extern __shared__ __nv_bfloat16 sm_g[];

    const __nv_bfloat16* Bh = (blockIdx.z == 0) ? Bh0 : (blockIdx.z == 1) ? Bh1 : Bh2;
    const __nv_bfloat16* Bl = (blockIdx.z == 0) ? Bl0 : (blockIdx.z == 1) ? Bl1 : Bl2;
    float*               C  = (blockIdx.z == 0) ? C0  : (blockIdx.z == 1) ? C1  : C2;

    const int tid  = threadIdx.x;
    const int lane = tid & 31;
    const int wid  = tid >> 5;
    const int wm   = wid >> 2;      // 0..1
    const int wn   = wid & 3;       // 0..3
    const int bm   = blockIdx.y << 7;
    const int bn   = blockIdx.x << 7;

    // copy slots: 512 chunks of 16B per tile; thread handles ids tid, tid+256
    const int row0 = tid >> 2,        ch0 = tid & 3;
    const int row1 = (tid + 256) >> 2, ch1 = (tid + 256) & 3;

    const size_t ga0 = (size_t)(bm + row0) * K + ch0 * 8;
    const size_t ga1 = (size_t)(bm + row1) * K + ch1 * 8;
    const size_t gb0 = (size_t)(bn + row0) * K + ch0 * 8;
    const size_t gb1 = (size_t)(bn + row1) * K + ch1 * 8;

    const int s0 = row0 * 40 + ch0 * 8;   // smem element offsets
    const int s1 = row1 * 40 + ch1 * 8;

    __nv_bfloat16* sAh = sm_g;
    __nv_bfloat16* sAl = sm_g + TILE_ELEM;
    __nv_bfloat16* sBh = sm_g + 2 * TILE_ELEM;
    __nv_bfloat16* sBl = sm_g + 3 * TILE_ELEM;

    const uint32_t base_u32 = smem_u32(sm_g);

    float acc[4][4][4];
#pragma unroll
    for (int i = 0; i < 4; i++)
#pragma unroll
        for (int j = 0; j < 4; j++)
#pragma unroll
            for (int r = 0; r < 4; r++) acc[i][j][r] = 0.f;

    // ldmatrix lane-address components (element row within tile, chunk)
    const int a_row = wm * 64 + (lane & 15);          // + mt*16
    const int a_ch  = lane >> 4;                      // 0..1
    const int b_row = wn * 32 + (lane & 7) + ((lane >> 4) << 3);  // + nt16*16
    const int b_ch  = (lane >> 3) & 1;

    // prologue: fill stage 0
    {
        *(uint4*)(sAh + s0) = *(const uint4*)(Ah + ga0);
        *(uint4*)(sAh + s1) = *(const uint4*)(Ah + ga1);
        *(uint4*)(sAl + s0) = *(const uint4*)(Al + ga0);
        *(uint4*)(sAl + s1) = *(const uint4*)(Al + ga1);
        *(uint4*)(sBh + s0) = *(const uint4*)(Bh + gb0);
        *(uint4*)(sBh + s1) = *(const uint4*)(Bh + gb1);
        *(uint4*)(sBl + s0) = *(const uint4*)(Bl + gb0);
        *(uint4*)(sBl + s1) = *(const uint4*)(Bl + gb1);
    }
    __syncthreads();

    for (int k0 = 0; k0 < K; k0 += 32) {
        const int cur = (k0 >> 5) & 1;
        const int nxt = cur ^ 1;
        const bool more = (k0 + 32) < K;

        uint4 rAh0, rAh1, rAl0, rAl1, rBh0, rBh1, rBl0, rBl1;
        if (more) {
            const int kn = k0 + 32;
            rAh0 = *(const uint4*)(Ah + ga0 + kn);
            rAh1 = *(const uint4*)(Ah + ga1 + kn);
            rAl0 = *(const uint4*)(Al + ga0 + kn);
            rAl1 = *(const uint4*)(Al + ga1 + kn);
            rBh0 = *(const uint4*)(Bh + gb0 + kn);
            rBh1 = *(const uint4*)(Bh + gb1 + kn);
            rBl0 = *(const uint4*)(Bl + gb0 + kn);
            rBl1 = *(const uint4*)(Bl + gb1 + kn);
        }

        const uint32_t stage = base_u32 + cur * (STAGE_ELEM * 2);

#pragma unroll
        for (int kh = 0; kh < 2; kh++) {
            uint32_t ah[4][4], al[4][4], bh[4][2], bl[4][2];
#pragma unroll
            for (int mt = 0; mt < 4; mt++) {
                uint32_t addr = stage + (a_row + mt * 16) * 80 + (2 * kh + a_ch) * 16;
                ldsm4(ah[mt][0], ah[mt][1], ah[mt][2], ah[mt][3], addr);
                ldsm4(al[mt][0], al[mt][1], al[mt][2], al[mt][3],
                      addr + TILE_ELEM * 2);
            }
#pragma unroll
            for (int nt = 0; nt < 2; nt++) {
                uint32_t addr = stage + 2 * TILE_ELEM * 2 +
                                (b_row + nt * 16) * 80 + (2 * kh + b_ch) * 16;
                ldsm4(bh[nt * 2][0], bh[nt * 2][1], bh[nt * 2 + 1][0], bh[nt * 2 + 1][1], addr);
                ldsm4(bl[nt * 2][0], bl[nt * 2][1], bl[nt * 2 + 1][0], bl[nt * 2 + 1][1],
                      addr + TILE_ELEM * 2);
            }
#pragma unroll
            for (int mt = 0; mt < 4; mt++)
#pragma unroll
                for (int n8 = 0; n8 < 4; n8++) {
                    mma16816(acc[mt][n8], ah[mt], bh[n8]);
                    mma16816(acc[mt][n8], ah[mt], bl[n8]);
                    mma16816(acc[mt][n8], al[mt], bh[n8]);
                }
        }

        if (more) {
            __nv_bfloat16* dAh = sm_g + nxt * STAGE_ELEM;
            *(uint4*)(dAh + s0)                 = rAh0;
            *(uint4*)(dAh + s1)                 = rAh1;
            *(uint4*)(dAh + TILE_ELEM + s0)     = rAl0;
            *(uint4*)(dAh + TILE_ELEM + s1)     = rAl1;
            *(uint4*)(dAh + 2 * TILE_ELEM + s0) = rBh0;
            *(uint4*)(dAh + 2 * TILE_ELEM + s1) = rBh1;
            *(uint4*)(dAh + 3 * TILE_ELEM + s0) = rBl0;
            *(uint4*)(dAh + 3 * TILE_ELEM + s1) = rBl1;
        }
        __syncthreads();
    }

    // epilogue
#pragma unroll
    for (int mt = 0; mt < 4; mt++) {
        const int gm = bm + wm * 64 + mt * 16 + (lane >> 2);
#pragma unroll
        for (int n8 = 0; n8 < 4; n8++) {
            const int gc = bn + wn * 32 + n8 * 8 + ((lane & 3) << 1);
            *(float2*)(&C[(size_t)gm * N + gc]) =
                make_float2(acc[mt][n8][0], acc[mt][n8][1]);
            *(float2*)(&C[(size_t)(gm + 8) * N + gc]) =
                make_float2(acc[mt][n8][2], acc[mt][n8][3]);
        }
    }
}

// ---------------------------------------------------------------------------
// RoPE applied in place to g_q and g_k, using precomputed inv_freq.
// ---------------------------------------------------------------------------
__global__ __launch_bounds__(256) void rope_kernel()
{
    int idx = blockIdx.x * 256 + threadIdx.x;   // exact: CM*CH*64 threads
    int i = idx & 63;
    int m = idx >> 10;
    int s = m & (CS - 1);

    float inv = g_invf[i];
    float ang = (float)s * inv;
    float c, sn;
    sincosf(ang, &sn, &c);

    int h = (idx >> 6) & (CH - 1);
    size_t base = (size_t)m * CD + (size_t)h * CHD;
    float q1 = g_q[base + i], q2 = g_q[base + i + 64];
    g_q[base + i]      = q1 * c - q2 * sn;
    g_q[base + i + 64] = q2 * c + q1 * sn;
    float k1 = g_k[base + i], k2 = g_k[base + i + 64];
    g_k[base + i]      = k1 * c - k2 * sn;
    g_k[base + i + 64] = k2 * c + k1 * sn;
}

// ---------------------------------------------------------------------------
// Flash attention (fp32 CUDA cores), epilogue writes bf16 hi/lo directly.
// ---------------------------------------------------------------------------
#define TPAD 132
#define FLASH_SMEM ((3 * 128 * TPAD + 3 * 128) * sizeof(float))

__global__ __launch_bounds__(256) void flash_attn(const float* __restrict__ mask)
{
    extern __shared__ float sm[];
    float* Qs  = sm;
    float* KVs = sm + 128 * TPAD;
    float* Ss  = sm + 2 * 128 * TPAD;
    float* m_s  = sm + 3 * 128 * TPAD;
    float* l_s  = m_s + 128;
    float* al_s = l_s + 128;

    const int tid = threadIdx.x;
    const int tx = tid & 15;
    const int ty = tid >> 4;
    const int b  = blockIdx.z;
    const int h  = blockIdx.y;
    const int q0 = blockIdx.x << 7;

    const float* Qg = g_q + ((size_t)(b * CS + q0)) * CD + (size_t)h * CHD;
    const float* Kg = g_k + ((size_t)b * CS) * CD + (size_t)h * CHD;
    const float* Vg = g_v + ((size_t)b * CS) * CD + (size_t)h * CHD;

    for (int idx = tid * 4; idx < 128 * 128; idx += 1024) {
        int ql = idx >> 7;
        int dd = idx & 127;
        float4 v = *(const float4*)(Qg + (size_t)ql * CD + dd);
        Qs[(dd + 0) * TPAD + ql] = v.x;
        Qs[(dd + 1) * TPAD + ql] = v.y;
        Qs[(dd + 2) * TPAD + ql] = v.z;
        Qs[(dd + 3) * TPAD + ql] = v.w;
    }
    if (tid < 128) { m_s[tid] = -INFINITY; l_s[tid] = 0.f; }

    float acc[8][8];
#pragma unroll
    for (int i = 0; i < 8; i++)
#pragma unroll
        for (int j = 0; j < 8; j++) acc[i][j] = 0.f;

    for (int kt = 0; kt < CS / 128; kt++) {
        const int k0 = kt << 7;
        __syncthreads();
        for (int idx = tid * 4; idx < 128 * 128; idx += 1024) {
            int kl = idx >> 7;
            int dd = idx & 127;
            float4 v = *(const float4*)(Kg + (size_t)(k0 + kl) * CD + dd);
            KVs[(dd + 0) * TPAD + kl] = v.x;
            KVs[(dd + 1) * TPAD + kl] = v.y;
            KVs[(dd + 2) * TPAD + kl] = v.z;
            KVs[(dd + 3) * TPAD + kl] = v.w;
        }
        __syncthreads();

        float sacc[8][8];
#pragma unroll
        for (int i = 0; i < 8; i++)
#pragma unroll
            for (int j = 0; j < 8; j++) sacc[i][j] = 0.f;

#pragma unroll 4
        for (int dd = 0; dd < 128; dd++) {
            float a[8], bb[8];
            *(float4*)(a)      = *(const float4*)(&Qs[dd * TPAD + (ty << 3)]);
            *(float4*)(a + 4)  = *(const float4*)(&Qs[dd * TPAD + (ty << 3) + 4]);
            *(float4*)(bb)     = *(const float4*)(&KVs[dd * TPAD + (tx << 3)]);
            *(float4*)(bb + 4) = *(const float4*)(&KVs[dd * TPAD + (tx << 3) + 4]);
#pragma unroll
            for (int i = 0; i < 8; i++)
#pragma unroll
                for (int j = 0; j < 8; j++)
                    sacc[i][j] = fmaf(a[i], bb[j], sacc[i][j]);
        }
#pragma unroll
        for (int i = 0; i < 8; i++) {
            float* sp = &Ss[((ty << 3) + i) * TPAD + (tx << 3)];
            *(float4*)(sp)     = make_float4(sacc[i][0], sacc[i][1], sacc[i][2], sacc[i][3]);
            *(float4*)(sp + 4) = make_float4(sacc[i][4], sacc[i][5], sacc[i][6], sacc[i][7]);
        }
        __syncthreads();

        for (int idx = tid * 4; idx < 128 * 128; idx += 1024) {
            int kl = idx >> 7;
            int dd = idx & 127;
            float4 v = *(const float4*)(Vg + (size_t)(k0 + kl) * CD + dd);
            *(float4*)(&KVs[kl * TPAD + dd]) = v;
        }

        {
            const int r  = tid >> 1;
            const int hf = tid & 1;
            const float* mrow = mask + ((size_t)b * CS + (q0 + r)) * CS + k0 + hf * 64;
            float* srow = &Ss[r * TPAD + hf * 64];
            float mprev = m_s[r];
            float lprev = l_s[r];

            float mx = -INFINITY;
#pragma unroll 4
            for (int c4 = 0; c4 < 16; c4++) {
                float4 mv = *(const float4*)(mrow + c4 * 4);
                float4 sv = *(float4*)(srow + c4 * 4);
                sv.x = sv.x * SCALE + mv.x;
                sv.y = sv.y * SCALE + mv.y;
                sv.z = sv.z * SCALE + mv.z;
                sv.w = sv.w * SCALE + mv.w;
                *(float4*)(srow + c4 * 4) = sv;
                mx = fmaxf(mx, fmaxf(fmaxf(sv.x, sv.y), fmaxf(sv.z, sv.w)));
            }
            mx = fmaxf(mx, __shfl_xor_sync(0xffffffffu, mx, 1));
            mx = fmaxf(mx, mprev);

            float sum = 0.f;
#pragma unroll 4
            for (int c4 = 0; c4 < 16; c4++) {
                float4 sv = *(float4*)(srow + c4 * 4);
                sv.x = __expf(sv.x - mx);
                sv.y = __expf(sv.y - mx);
                sv.z = __expf(sv.z - mx);
                sv.w = __expf(sv.w - mx);
                *(float4*)(srow + c4 * 4) = sv;
                sum += sv.x + sv.y + sv.z + sv.w;
            }
            sum += __shfl_xor_sync(0xffffffffu, sum, 1);

            if (hf == 0) {
                float al = __expf(mprev - mx);
                m_s[r]  = mx;
                l_s[r]  = lprev * al + sum;
                al_s[r] = al;
            }
        }
        __syncthreads();

#pragma unroll
        for (int i = 0; i < 8; i++) {
            float al = al_s[(ty << 3) + i];
#pragma unroll
            for (int j = 0; j < 8; j++) acc[i][j] *= al;
        }
#pragma unroll 2
        for (int kk = 0; kk < 128; kk++) {
            float bb[8];
            *(float4*)(bb)     = *(const float4*)(&KVs[kk * TPAD + (tx << 3)]);
            *(float4*)(bb + 4) = *(const float4*)(&KVs[kk * TPAD + (tx << 3) + 4]);
#pragma unroll
            for (int i = 0; i < 8; i++) {
                float p = Ss[((ty << 3) + i) * TPAD + kk];
#pragma unroll
                for (int j = 0; j < 8; j++)
                    acc[i][j] = fmaf(p, bb[j], acc[i][j]);
            }
        }
    }

    // epilogue: divide by l, write bf16 hi/lo for the O projection
    size_t obase = ((size_t)(b * CS + q0)) * CD + (size_t)h * CHD;
#pragma unroll
    for (int i = 0; i < 8; i++) {
        float inv = 1.0f / l_s[(ty << 3) + i];
        size_t off = obase + (size_t)((ty << 3) + i) * CD + (tx << 3);
        __nv_bfloat162 hv[4], lv[4];
#pragma unroll
        for (int j2 = 0; j2 < 4; j2++) {
            float o0 = acc[i][2 * j2]     * inv;
            float o1 = acc[i][2 * j2 + 1] * inv;
            __nv_bfloat16 h0 = __float2bfloat16_rn(o0);
            __nv_bfloat16 h1 = __float2bfloat16_rn(o1);
            hv[j2] = __nv_bfloat162(h0, h1);
            lv[j2] = __nv_bfloat162(__float2bfloat16_rn(o0 - __bfloat162float(h0)),
                                    __float2bfloat16_rn(o1 - __bfloat162float(h1)));
        }
        *(uint4*)(&g_aoh[off]) = *(uint4*)hv;
        *(uint4*)(&g_aol[off]) = *(uint4*)lv;
    }
}

// ---------------------------------------------------------------------------
extern "C" void kernel_launch(void* const* d_in, const int* in_sizes, int n_in,
                              void* d_out, int out_size)
{
    const float* X    = (const float*)d_in[0];
    const float* mask = (const float*)d_in[1];
    const float* Wq   = (const float*)d_in[2];
    const float* Wk   = (const float*)d_in[3];
    const float* Wv   = (const float*)d_in[4];
    const float* Wo   = (const float*)d_in[5];
    float* out = (float*)d_out;

    float *qp, *kp, *vp;
    cudaGetSymbolAddress((void**)&qp, g_q);
    cudaGetSymbolAddress((void**)&kp, g_k);
    cudaGetSymbolAddress((void**)&vp, g_v);
    __nv_bfloat16 *xh, *xl, *wqh, *wql, *wkh, *wkl, *wvh, *wvl, *woh, *wol, *aoh, *aol;
    cudaGetSymbolAddress((void**)&xh,  g_xh);
    cudaGetSymbolAddress((void**)&xl,  g_xl);
    cudaGetSymbolAddress((void**)&wqh, g_wqh);
    cudaGetSymbolAddress((void**)&wql, g_wql);
    cudaGetSymbolAddress((void**)&wkh, g_wkh);
    cudaGetSymbolAddress((void**)&wkl, g_wkl);
    cudaGetSymbolAddress((void**)&wvh, g_wvh);
    cudaGetSymbolAddress((void**)&wvl, g_wvl);
    cudaGetSymbolAddress((void**)&woh, g_woh);
    cudaGetSymbolAddress((void**)&wol, g_wol);
    cudaGetSymbolAddress((void**)&aoh, g_aoh);
    cudaGetSymbolAddress((void**)&aol, g_aol);

    cudaFuncSetAttribute(flash_attn, cudaFuncAttributeMaxDynamicSharedMemorySize,
                         (int)FLASH_SMEM);
    cudaFuncSetAttribute(gemm_bf16x3, cudaFuncAttributeMaxDynamicSharedMemorySize,
                         GEMM_SMEM);

    init_invf<<<1, 64>>>();

    const int n4x = CM * CD / 4, n4w = CD * CD / 4;
    convert_hilo<<<n4x / 256, 256>>>(X,  xh,  xl,  n4x);
    convert_hilo<<<n4w / 256, 256>>>(Wq, wqh, wql, n4w);
    convert_hilo<<<n4w / 256, 256>>>(Wk, wkh, wkl, n4w);
    convert_hilo<<<n4w / 256, 256>>>(Wv, wvh, wvl, n4w);
    convert_hilo<<<n4w / 256, 256>>>(Wo, woh, wol, n4w);

    // fused Q/K/V projections
    gemm_bf16x3<<<dim3(CD / 128, CM / 128, 3), 256, GEMM_SMEM>>>(
        xh, xl, wqh, wql, wkh, wkl, wvh, wvl, qp, kp, vp, CD, CD);

    rope_kernel<<<(CM * CH * 64) / 256, 256>>>();

    flash_attn<<<dim3(CS / 128, CH, CB), 256, FLASH_SMEM>>>(mask);

    // O projection
    gemm_bf16x3<<<dim3(CD / 128, CM / 128, 1), 256, GEMM_SMEM>>>(
        aoh, aol, woh, wol, woh, wol, woh, wol, out, out, out, CD, CD);
}

// round 4
// speedup vs baseline: 3.0580x; 1.6724x over previous
#include <cuda_runtime.h>
#include <cuda_bf16.h>
#include <math.h>
#include <stdint.h>

#define CB 2
#define CS 2048
#define CD 2048
#define CH 16
#define CHD 128
#define CM (CB*CS)          // 4096 rows total
#define SCALE 0.08838834764831845f   // 1/sqrt(128)

// ---------------------------------------------------------------------------
// Scratch (allocation-free rule: static device globals)
// ---------------------------------------------------------------------------
__device__ float g_q[(size_t)CM * CD];
__device__ float g_k[(size_t)CM * CD];
__device__ float g_invf[64];

__device__ __nv_bfloat16 g_xh[(size_t)CM * CD];
__device__ __nv_bfloat16 g_xl[(size_t)CM * CD];
__device__ __nv_bfloat16 g_wqh[(size_t)CD * CD];
__device__ __nv_bfloat16 g_wql[(size_t)CD * CD];
__device__ __nv_bfloat16 g_wkh[(size_t)CD * CD];
__device__ __nv_bfloat16 g_wkl[(size_t)CD * CD];
__device__ __nv_bfloat16 g_wvh[(size_t)CD * CD];
__device__ __nv_bfloat16 g_wvl[(size_t)CD * CD];
__device__ __nv_bfloat16 g_woh[(size_t)CD * CD];
__device__ __nv_bfloat16 g_wol[(size_t)CD * CD];
__device__ __nv_bfloat16 g_aoh[(size_t)CM * CD];
__device__ __nv_bfloat16 g_aol[(size_t)CM * CD];

// bf16 hi/lo planes for attention inputs
__device__ __nv_bfloat16 g_qh[(size_t)CM * CD];
__device__ __nv_bfloat16 g_ql[(size_t)CM * CD];
__device__ __nv_bfloat16 g_kh[(size_t)CM * CD];
__device__ __nv_bfloat16 g_kl[(size_t)CM * CD];
__device__ __nv_bfloat16 g_vh[(size_t)CM * CD];
__device__ __nv_bfloat16 g_vl[(size_t)CM * CD];

// ---------------------------------------------------------------------------
// PTX helpers
// ---------------------------------------------------------------------------
__device__ __forceinline__ uint32_t smem_u32(const void* p) {
    return (uint32_t)__cvta_generic_to_shared(p);
}

__device__ __forceinline__ void ldsm4(uint32_t& r0, uint32_t& r1,
                                      uint32_t& r2, uint32_t& r3, uint32_t addr) {
    asm volatile("ldmatrix.sync.aligned.m8n8.x4.shared.b16 {%0,%1,%2,%3}, [%4];"
                 : "=r"(r0), "=r"(r1), "=r"(r2), "=r"(r3) : "r"(addr));
}

__device__ __forceinline__ void ldsm4t(uint32_t& r0, uint32_t& r1,
                                       uint32_t& r2, uint32_t& r3, uint32_t addr) {
    asm volatile("ldmatrix.sync.aligned.m8n8.x4.trans.shared.b16 {%0,%1,%2,%3}, [%4];"
                 : "=r"(r0), "=r"(r1), "=r"(r2), "=r"(r3) : "r"(addr));
}

__device__ __forceinline__ void mma16816(float* c, const uint32_t* a, const uint32_t* b) {
    asm volatile(
        "mma.sync.aligned.m16n8k16.row.col.f32.bf16.bf16.f32 "
        "{%0,%1,%2,%3}, {%4,%5,%6,%7}, {%8,%9}, {%0,%1,%2,%3};"
        : "+f"(c[0]), "+f"(c[1]), "+f"(c[2]), "+f"(c[3])
        : "r"(a[0]), "r"(a[1]), "r"(a[2]), "r"(a[3]), "r"(b[0]), "r"(b[1]));
}

__device__ __forceinline__ uint32_t pack_bf16_hi(float a, float b) {
    __nv_bfloat162 v(__float2bfloat16_rn(a), __float2bfloat16_rn(b));
    return *(uint32_t*)&v;
}

// ---------------------------------------------------------------------------
__global__ void init_invf()
{
    int i = threadIdx.x;
    if (i < 64)
        g_invf[i] = (float)(1.0 / pow(10000.0, (double)(2 * i) / (double)CHD));
}

// ---------------------------------------------------------------------------
// fp32 -> (bf16 hi, bf16 lo) split conversion. 4 elements per thread.
// ---------------------------------------------------------------------------
__global__ __launch_bounds__(256) void convert_hilo(
    const float* __restrict__ src,
    __nv_bfloat16* __restrict__ hi, __nv_bfloat16* __restrict__ lo, int n4)
{
    int i = blockIdx.x * 256 + threadIdx.x;
    if (i >= n4) return;
    float4 v = ((const float4*)src)[i];
    __nv_bfloat16 h0 = __float2bfloat16_rn(v.x);
    __nv_bfloat16 h1 = __float2bfloat16_rn(v.y);
    __nv_bfloat16 h2 = __float2bfloat16_rn(v.z);
    __nv_bfloat16 h3 = __float2bfloat16_rn(v.w);
    __nv_bfloat16 l0 = __float2bfloat16_rn(v.x - __bfloat162float(h0));
    __nv_bfloat16 l1 = __float2bfloat16_rn(v.y - __bfloat162float(h1));
    __nv_bfloat16 l2 = __float2bfloat16_rn(v.z - __bfloat162float(h2));
    __nv_bfloat16 l3 = __float2bfloat16_rn(v.w - __bfloat162float(h3));
    ((__nv_bfloat162*)hi)[2 * i]     = __nv_bfloat162(h0, h1);
    ((__nv_bfloat162*)hi)[2 * i + 1] = __nv_bfloat162(h2, h3);
    ((__nv_bfloat162*)lo)[2 * i]     = __nv_bfloat162(l0, l1);
    ((__nv_bfloat162*)lo)[2 * i + 1] = __nv_bfloat162(l2, l3);
}

// ---------------------------------------------------------------------------
// bf16-split tensor-core NT GEMM. blockIdx.z == zbf writes bf16 hi/lo planes
// (used for V in the fused QKV launch); other z write fp32 C.
// ---------------------------------------------------------------------------
#define TILE_ELEM (128 * 40)
#define STAGE_ELEM (4 * TILE_ELEM)
#define GEMM_SMEM (2 * STAGE_ELEM * 2)

__global__ __launch_bounds__(256, 1) void gemm_bf16x3(
    const __nv_bfloat16* __restrict__ Ah, const __nv_bfloat16* __restrict__ Al,
    const __nv_bfloat16* __restrict__ Bh0, const __nv_bfloat16* __restrict__ Bl0,
    const __nv_bfloat16* __restrict__ Bh1, const __nv_bfloat16* __restrict__ Bl1,
    const __nv_bfloat16* __restrict__ Bh2, const __nv_bfloat16* __restrict__ Bl2,
    float* __restrict__ C0, float* __restrict__ C1,
    __nv_bfloat16* __restrict__ Cbh, __nv_bfloat16* __restrict__ Cbl, int zbf,
    int N, int K)
{
    extern __shared__ __nv_bfloat16 sm_g[];

    const __nv_bfloat16* Bh = (blockIdx.z == 0) ? Bh0 : (blockIdx.z == 1) ? Bh1 : Bh2;
    const __nv_bfloat16* Bl = (blockIdx.z == 0) ? Bl0 : (blockIdx.z == 1) ? Bl1 : Bl2;
    float*               C  = (blockIdx.z == 0) ? C0  : C1;

    const int tid  = threadIdx.x;
    const int lane = tid & 31;
    const int wid  = tid >> 5;
    const int wm   = wid >> 2;
    const int wn   = wid & 3;
    const int bm   = blockIdx.y << 7;
    const int bn   = blockIdx.x << 7;

    const int row0 = tid >> 2,         ch0 = tid & 3;
    const int row1 = (tid + 256) >> 2, ch1 = (tid + 256) & 3;

    const size_t ga0 = (size_t)(bm + row0) * K + ch0 * 8;
    const size_t ga1 = (size_t)(bm + row1) * K + ch1 * 8;
    const size_t gb0 = (size_t)(bn + row0) * K + ch0 * 8;
    const size_t gb1 = (size_t)(bn + row1) * K + ch1 * 8;

    const int s0 = row0 * 40 + ch0 * 8;
    const int s1 = row1 * 40 + ch1 * 8;

    __nv_bfloat16* sAh = sm_g;
    __nv_bfloat16* sAl = sm_g + TILE_ELEM;
    __nv_bfloat16* sBh = sm_g + 2 * TILE_ELEM;
    __nv_bfloat16* sBl = sm_g + 3 * TILE_ELEM;

    const uint32_t base_u32 = smem_u32(sm_g);

    float acc[4][4][4];
#pragma unroll
    for (int i = 0; i < 4; i++)
#pragma unroll
        for (int j = 0; j < 4; j++)
#pragma unroll
            for (int r = 0; r < 4; r++) acc[i][j][r] = 0.f;

    const int a_row = wm * 64 + (lane & 15);
    const int a_ch  = lane >> 4;
    const int b_row = wn * 32 + (lane & 7) + ((lane >> 4) << 3);
    const int b_ch  = (lane >> 3) & 1;

    {
        *(uint4*)(sAh + s0) = *(const uint4*)(Ah + ga0);
        *(uint4*)(sAh + s1) = *(const uint4*)(Ah + ga1);
        *(uint4*)(sAl + s0) = *(const uint4*)(Al + ga0);
        *(uint4*)(sAl + s1) = *(const uint4*)(Al + ga1);
        *(uint4*)(sBh + s0) = *(const uint4*)(Bh + gb0);
        *(uint4*)(sBh + s1) = *(const uint4*)(Bh + gb1);
        *(uint4*)(sBl + s0) = *(const uint4*)(Bl + gb0);
        *(uint4*)(sBl + s1) = *(const uint4*)(Bl + gb1);
    }
    __syncthreads();

    for (int k0 = 0; k0 < K; k0 += 32) {
        const int cur = (k0 >> 5) & 1;
        const int nxt = cur ^ 1;
        const bool more = (k0 + 32) < K;

        uint4 rAh0, rAh1, rAl0, rAl1, rBh0, rBh1, rBl0, rBl1;
        if (more) {
            const int kn = k0 + 32;
            rAh0 = *(const uint4*)(Ah + ga0 + kn);
            rAh1 = *(const uint4*)(Ah + ga1 + kn);
            rAl0 = *(const uint4*)(Al + ga0 + kn);
            rAl1 = *(const uint4*)(Al + ga1 + kn);
            rBh0 = *(const uint4*)(Bh + gb0 + kn);
            rBh1 = *(const uint4*)(Bh + gb1 + kn);
            rBl0 = *(const uint4*)(Bl + gb0 + kn);
            rBl1 = *(const uint4*)(Bl + gb1 + kn);
        }

        const uint32_t stage = base_u32 + cur * (STAGE_ELEM * 2);

#pragma unroll
        for (int kh = 0; kh < 2; kh++) {
            uint32_t ah[4][4], al[4][4], bh[4][2], bl[4][2];
#pragma unroll
            for (int mt = 0; mt < 4; mt++) {
                uint32_t addr = stage + (a_row + mt * 16) * 80 + (2 * kh + a_ch) * 16;
                ldsm4(ah[mt][0], ah[mt][1], ah[mt][2], ah[mt][3], addr);
                ldsm4(al[mt][0], al[mt][1], al[mt][2], al[mt][3],
                      addr + TILE_ELEM * 2);
            }
#pragma unroll
            for (int nt = 0; nt < 2; nt++) {
                uint32_t addr = stage + 2 * TILE_ELEM * 2 +
                                (b_row + nt * 16) * 80 + (2 * kh + b_ch) * 16;
                ldsm4(bh[nt * 2][0], bh[nt * 2][1], bh[nt * 2 + 1][0], bh[nt * 2 + 1][1], addr);
                ldsm4(bl[nt * 2][0], bl[nt * 2][1], bl[nt * 2 + 1][0], bl[nt * 2 + 1][1],
                      addr + TILE_ELEM * 2);
            }
#pragma unroll
            for (int mt = 0; mt < 4; mt++)
#pragma unroll
                for (int n8 = 0; n8 < 4; n8++) {
                    mma16816(acc[mt][n8], ah[mt], bh[n8]);
                    mma16816(acc[mt][n8], ah[mt], bl[n8]);
                    mma16816(acc[mt][n8], al[mt], bh[n8]);
                }
        }

        if (more) {
            __nv_bfloat16* dAh = sm_g + nxt * STAGE_ELEM;
            *(uint4*)(dAh + s0)                 = rAh0;
            *(uint4*)(dAh + s1)                 = rAh1;
            *(uint4*)(dAh + TILE_ELEM + s0)     = rAl0;
            *(uint4*)(dAh + TILE_ELEM + s1)     = rAl1;
            *(uint4*)(dAh + 2 * TILE_ELEM + s0) = rBh0;
            *(uint4*)(dAh + 2 * TILE_ELEM + s1) = rBh1;
            *(uint4*)(dAh + 3 * TILE_ELEM + s0) = rBl0;
            *(uint4*)(dAh + 3 * TILE_ELEM + s1) = rBl1;
        }
        __syncthreads();
    }

    if ((int)blockIdx.z == zbf) {
        // bf16 hi/lo epilogue (V path)
#pragma unroll
        for (int mt = 0; mt < 4; mt++) {
            const int gm = bm + wm * 64 + mt * 16 + (lane >> 2);
#pragma unroll
            for (int n8 = 0; n8 < 4; n8++) {
                const int gc = bn + wn * 32 + n8 * 8 + ((lane & 3) << 1);
#pragma unroll
                for (int hrow = 0; hrow < 2; hrow++) {
                    float o0 = acc[mt][n8][hrow * 2];
                    float o1 = acc[mt][n8][hrow * 2 + 1];
                    size_t off = (size_t)(gm + hrow * 8) * N + gc;
                    __nv_bfloat16 h0 = __float2bfloat16_rn(o0);
                    __nv_bfloat16 h1 = __float2bfloat16_rn(o1);
                    __nv_bfloat162 hv(h0, h1);
                    __nv_bfloat162 lv(__float2bfloat16_rn(o0 - __bfloat162float(h0)),
                                      __float2bfloat16_rn(o1 - __bfloat162float(h1)));
                    *(uint32_t*)(&Cbh[off]) = *(uint32_t*)&hv;
                    *(uint32_t*)(&Cbl[off]) = *(uint32_t*)&lv;
                }
            }
        }
    } else {
#pragma unroll
        for (int mt = 0; mt < 4; mt++) {
            const int gm = bm + wm * 64 + mt * 16 + (lane >> 2);
#pragma unroll
            for (int n8 = 0; n8 < 4; n8++) {
                const int gc = bn + wn * 32 + n8 * 8 + ((lane & 3) << 1);
                *(float2*)(&C[(size_t)gm * N + gc]) =
                    make_float2(acc[mt][n8][0], acc[mt][n8][1]);
                *(float2*)(&C[(size_t)(gm + 8) * N + gc]) =
                    make_float2(acc[mt][n8][2], acc[mt][n8][3]);
            }
        }
    }
}

// ---------------------------------------------------------------------------
// RoPE: reads fp32 g_q/g_k, writes bf16 hi/lo planes qh/ql/kh/kl.
// ---------------------------------------------------------------------------
__global__ __launch_bounds__(256) void rope_split()
{
    int idx = blockIdx.x * 256 + threadIdx.x;
    int i = idx & 63;
    int m = idx >> 10;
    int s = m & (CS - 1);

    float inv = g_invf[i];
    float ang = (float)s * inv;
    float c, sn;
    sincosf(ang, &sn, &c);

    int h = (idx >> 6) & (CH - 1);
    size_t base = (size_t)m * CD + (size_t)h * CHD;

    float q1 = g_q[base + i], q2 = g_q[base + i + 64];
    float rq1 = q1 * c - q2 * sn;
    float rq2 = q2 * c + q1 * sn;
    float k1 = g_k[base + i], k2 = g_k[base + i + 64];
    float rk1 = k1 * c - k2 * sn;
    float rk2 = k2 * c + k1 * sn;

    __nv_bfloat16 h1 = __float2bfloat16_rn(rq1);
    __nv_bfloat16 h2 = __float2bfloat16_rn(rq2);
    g_qh[base + i]      = h1;
    g_qh[base + i + 64] = h2;
    g_ql[base + i]      = __float2bfloat16_rn(rq1 - __bfloat162float(h1));
    g_ql[base + i + 64] = __float2bfloat16_rn(rq2 - __bfloat162float(h2));

    __nv_bfloat16 h3 = __float2bfloat16_rn(rk1);
    __nv_bfloat16 h4 = __float2bfloat16_rn(rk2);
    g_kh[base + i]      = h3;
    g_kh[base + i + 64] = h4;
    g_kl[base + i]      = __float2bfloat16_rn(rk1 - __bfloat162float(h3));
    g_kl[base + i + 64] = __float2bfloat16_rn(rk2 - __bfloat162float(h4));
}

// ---------------------------------------------------------------------------
// Tensor-core flash attention.
// CTA: 128 q rows x full K sweep for one (b, h). 8 warps as 2x4 (64x32 warp
// tiles for both S and PV phases).
// smem: Qh/Ql [128x136 bf16], KVh/KVl [128x136 bf16] (K then V),
//       S [128x132 fp32] (reused in-place for P bf16 hi/lo planes), stats.
// ---------------------------------------------------------------------------
#define QSTR 136                 // bf16 elems per row (272 B, 17 chunks: odd)
#define SSTRF 132                // floats per row (528 B, 33 chunks: odd)
#define OFF_QH  0
#define OFF_QL  34816
#define OFF_KH  69632
#define OFF_KL  104448
#define OFF_S   139264
#define OFF_ST  206848           // stats
#define FLASH_SMEM 208384

__global__ __launch_bounds__(256, 1) void flash_mma(const float* __restrict__ mask)
{
    extern __shared__ char smc[];
    __nv_bfloat16* sQh = (__nv_bfloat16*)(smc + OFF_QH);
    __nv_bfloat16* sQl = (__nv_bfloat16*)(smc + OFF_QL);
    __nv_bfloat16* sKh = (__nv_bfloat16*)(smc + OFF_KH);
    __nv_bfloat16* sKl = (__nv_bfloat16*)(smc + OFF_KL);
    float* sS   = (float*)(smc + OFF_S);
    float* m_s  = (float*)(smc + OFF_ST);
    float* l_s  = m_s + 128;
    float* al_s = l_s + 128;

    const int tid  = threadIdx.x;
    const int lane = tid & 31;
    const int wid  = tid >> 5;
    const int wm   = wid >> 2;      // 0..1
    const int wn   = wid & 3;       // 0..3
    const int b    = blockIdx.z;
    const int h    = blockIdx.y;
    const int q0   = blockIdx.x << 7;

    const __nv_bfloat16* Qhg = g_qh + (size_t)(b * CS + q0) * CD + (size_t)h * CHD;
    const __nv_bfloat16* Qlg = g_ql + (size_t)(b * CS + q0) * CD + (size_t)h * CHD;
    const __nv_bfloat16* Khg = g_kh + (size_t)(b * CS) * CD + (size_t)h * CHD;
    const __nv_bfloat16* Klg = g_kl + (size_t)(b * CS) * CD + (size_t)h * CHD;
    const __nv_bfloat16* Vhg = g_vh + (size_t)(b * CS) * CD + (size_t)h * CHD;
    const __nv_bfloat16* Vlg = g_vl + (size_t)(b * CS) * CD + (size_t)h * CHD;

    // load Q planes (rows 128, 256B payload per row)
    for (int i = tid; i < 2048; i += 256) {
        int r = i >> 4, c = i & 15;
        *(uint4*)(sQh + r * QSTR + c * 8) = *(const uint4*)(Qhg + (size_t)r * CD + c * 8);
        *(uint4*)(sQl + r * QSTR + c * 8) = *(const uint4*)(Qlg + (size_t)r * CD + c * 8);
    }
    if (tid < 128) { m_s[tid] = -INFINITY; l_s[tid] = 0.f; }

    float oacc[4][4][4];
#pragma unroll
    for (int i = 0; i < 4; i++)
#pragma unroll
        for (int j = 0; j < 4; j++)
#pragma unroll
            for (int r = 0; r < 4; r++) oacc[i][j][r] = 0.f;

    const uint32_t sQ_u  = smem_u32(smc) + OFF_QH;
    const uint32_t sKV_u = smem_u32(smc) + OFF_KH;
    const uint32_t sS_u  = smem_u32(smc) + OFF_S;

    // lane address components
    const int a_r = wm * 64 + (lane & 15);                 // + mt*16 (A rows)
    const int a_c = lane >> 4;                             // chunk parity
    const int b_r = wn * 32 + (lane & 7) + ((lane >> 4) << 3);  // + nt*16 (B rows)
    const int b_c = (lane >> 3) & 1;
    const int v_key = ((lane >> 3) & 1) * 8 + (lane & 7);  // + t*16
    const int v_dd  = wn * 32 + ((lane >> 4) << 3);        // + jj*16

    for (int kt = 0; kt < CS / 128; kt++) {
        const int k0 = kt << 7;
        __syncthreads();   // guard KV/S reuse from previous iteration

        // load K planes
        for (int i = tid; i < 2048; i += 256) {
            int r = i >> 4, c = i & 15;
            *(uint4*)(sKh + r * QSTR + c * 8) =
                *(const uint4*)(Khg + (size_t)(k0 + r) * CD + c * 8);
            *(uint4*)(sKl + r * QSTR + c * 8) =
                *(const uint4*)(Klg + (size_t)(k0 + r) * CD + c * 8);
        }
        __syncthreads();

        // ---- S = Q K^T (bf16x3) ----
        float sacc[4][4][4];
#pragma unroll
        for (int i = 0; i < 4; i++)
#pragma unroll
            for (int j = 0; j < 4; j++)
#pragma unroll
                for (int r = 0; r < 4; r++) sacc[i][j][r] = 0.f;

#pragma unroll
        for (int t = 0; t < 8; t++) {
            uint32_t ah[4][4], al[4][4], bh[4][2], bl[4][2];
#pragma unroll
            for (int mt = 0; mt < 4; mt++) {
                uint32_t addr = sQ_u + (a_r + mt * 16) * 272 + (t * 2 + a_c) * 16;
                ldsm4(ah[mt][0], ah[mt][1], ah[mt][2], ah[mt][3], addr);
                ldsm4(al[mt][0], al[mt][1], al[mt][2], al[mt][3], addr + 34816);
            }
#pragma unroll
            for (int nt = 0; nt < 2; nt++) {
                uint32_t addr = sKV_u + (b_r + nt * 16) * 272 + (t * 2 + b_c) * 16;
                ldsm4(bh[nt*2][0], bh[nt*2][1], bh[nt*2+1][0], bh[nt*2+1][1], addr);
                ldsm4(bl[nt*2][0], bl[nt*2][1], bl[nt*2+1][0], bl[nt*2+1][1], addr + 34816);
            }
#pragma unroll
            for (int mt = 0; mt < 4; mt++)
#pragma unroll
                for (int j = 0; j < 4; j++) {
                    mma16816(sacc[mt][j], ah[mt], bh[j]);
                    mma16816(sacc[mt][j], ah[mt], bl[j]);
                    mma16816(sacc[mt][j], al[mt], bh[j]);
                }
        }

        // store S fp32
#pragma unroll
        for (int mt = 0; mt < 4; mt++) {
            const int r1 = wm * 64 + mt * 16 + (lane >> 2);
#pragma unroll
            for (int j = 0; j < 4; j++) {
                const int cc = wn * 32 + j * 8 + ((lane & 3) << 1);
                *(float2*)(&sS[r1 * SSTRF + cc]) =
                    make_float2(sacc[mt][j][0], sacc[mt][j][1]);
                *(float2*)(&sS[(r1 + 8) * SSTRF + cc]) =
                    make_float2(sacc[mt][j][2], sacc[mt][j][3]);
            }
        }
        __syncthreads();

        // load V planes (overwrite K region)
        for (int i = tid; i < 2048; i += 256) {
            int r = i >> 4, c = i & 15;
            *(uint4*)(sKh + r * QSTR + c * 8) =
                *(const uint4*)(Vhg + (size_t)(k0 + r) * CD + c * 8);
            *(uint4*)(sKl + r * QSTR + c * 8) =
                *(const uint4*)(Vlg + (size_t)(k0 + r) * CD + c * 8);
        }

        // ---- online softmax (registers), write P bf16 hi/lo in place ----
        {
            const int r  = tid >> 1;
            const int hf = tid & 1;
            const float* mrow = mask + ((size_t)b * CS + (q0 + r)) * CS + k0 + hf * 64;
            const float* srow = sS + r * SSTRF + hf * 64;
            float v[64];
            float mprev = m_s[r];
            float lprev = l_s[r];

            float mx = -INFINITY;
#pragma unroll
            for (int c4 = 0; c4 < 16; c4++) {
                float4 sv = *(const float4*)(srow + c4 * 4);
                float4 mv = *(const float4*)(mrow + c4 * 4);
                v[c4*4+0] = sv.x * SCALE + mv.x;
                v[c4*4+1] = sv.y * SCALE + mv.y;
                v[c4*4+2] = sv.z * SCALE + mv.z;
                v[c4*4+3] = sv.w * SCALE + mv.w;
                mx = fmaxf(mx, fmaxf(fmaxf(v[c4*4+0], v[c4*4+1]),
                                     fmaxf(v[c4*4+2], v[c4*4+3])));
            }
            mx = fmaxf(mx, __shfl_xor_sync(0xffffffffu, mx, 1));
            mx = fmaxf(mx, mprev);

            float sum = 0.f;
#pragma unroll
            for (int i = 0; i < 64; i++) {
                v[i] = __expf(v[i] - mx);
                sum += v[i];
            }
            sum += __shfl_xor_sync(0xffffffffu, sum, 1);

            __syncwarp();   // all reads of S row done before P overwrites it

            __nv_bfloat16* ph = (__nv_bfloat16*)((char*)sS + r * (SSTRF*4)) + hf * 64;
            __nv_bfloat16* pl = (__nv_bfloat16*)((char*)sS + r * (SSTRF*4) + 256) + hf * 64;
#pragma unroll
            for (int i = 0; i < 64; i += 4) {
                __nv_bfloat16 h0 = __float2bfloat16_rn(v[i]);
                __nv_bfloat16 h1 = __float2bfloat16_rn(v[i+1]);
                __nv_bfloat16 h2 = __float2bfloat16_rn(v[i+2]);
                __nv_bfloat16 h3 = __float2bfloat16_rn(v[i+3]);
                __nv_bfloat162 hp0(h0, h1), hp1(h2, h3);
                __nv_bfloat162 lp0(__float2bfloat16_rn(v[i]   - __bfloat162float(h0)),
                                   __float2bfloat16_rn(v[i+1] - __bfloat162float(h1)));
                __nv_bfloat162 lp1(__float2bfloat16_rn(v[i+2] - __bfloat162float(h2)),
                                   __float2bfloat16_rn(v[i+3] - __bfloat162float(h3)));
                uint2 hw = make_uint2(*(uint32_t*)&hp0, *(uint32_t*)&hp1);
                uint2 lw = make_uint2(*(uint32_t*)&lp0, *(uint32_t*)&lp1);
                *(uint2*)(ph + i) = hw;
                *(uint2*)(pl + i) = lw;
            }

            if (hf == 0) {
                float al = __expf(mprev - mx);
                m_s[r]  = mx;
                l_s[r]  = lprev * al + sum;
                al_s[r] = al;
            }
        }
        __syncthreads();

        // rescale output accumulator
#pragma unroll
        for (int mt = 0; mt < 4; mt++) {
            const int r1 = wm * 64 + mt * 16 + (lane >> 2);
            float al1 = al_s[r1];
            float al2 = al_s[r1 + 8];
#pragma unroll
            for (int j = 0; j < 4; j++) {
                oacc[mt][j][0] *= al1;
                oacc[mt][j][1] *= al1;
                oacc[mt][j][2] *= al2;
                oacc[mt][j][3] *= al2;
            }
        }

        // ---- O += P V (bf16x3) ----
#pragma unroll
        for (int t = 0; t < 8; t++) {
            uint32_t pa[4][4], pb[4][4], vh_[2][4], vl_[2][4];
#pragma unroll
            for (int mt = 0; mt < 4; mt++) {
                uint32_t addr = sS_u + (a_r + mt * 16) * 528 + t * 32 + a_c * 16;
                ldsm4(pa[mt][0], pa[mt][1], pa[mt][2], pa[mt][3], addr);
                ldsm4(pb[mt][0], pb[mt][1], pb[mt][2], pb[mt][3], addr + 256);
            }
#pragma unroll
            for (int jj = 0; jj < 2; jj++) {
                uint32_t addr = sKV_u + (t * 16 + v_key) * 272 + (v_dd + jj * 16) * 2;
                ldsm4t(vh_[jj][0], vh_[jj][1], vh_[jj][2], vh_[jj][3], addr);
                ldsm4t(vl_[jj][0], vl_[jj][1], vl_[jj][2], vl_[jj][3], addr + 34816);
            }
#pragma unroll
            for (int mt = 0; mt < 4; mt++)
#pragma unroll
                for (int n8 = 0; n8 < 4; n8++) {
                    const int jj = n8 >> 1, p = (n8 & 1) * 2;
                    uint32_t bH[2] = { vh_[jj][p], vh_[jj][p + 1] };
                    uint32_t bL[2] = { vl_[jj][p], vl_[jj][p + 1] };
                    mma16816(oacc[mt][n8], pa[mt], bH);
                    mma16816(oacc[mt][n8], pa[mt], bL);
                    mma16816(oacc[mt][n8], pb[mt], bH);
                }
        }
    }

    // epilogue: /l, bf16 hi/lo split store
#pragma unroll
    for (int mt = 0; mt < 4; mt++) {
        const int r1 = wm * 64 + mt * 16 + (lane >> 2);
        float inv1 = 1.0f / l_s[r1];
        float inv2 = 1.0f / l_s[r1 + 8];
#pragma unroll
        for (int n8 = 0; n8 < 4; n8++) {
            const int cc = wn * 32 + n8 * 8 + ((lane & 3) << 1);
#pragma unroll
            for (int hrow = 0; hrow < 2; hrow++) {
                float o0 = oacc[mt][n8][hrow * 2]     * (hrow ? inv2 : inv1);
                float o1 = oacc[mt][n8][hrow * 2 + 1] * (hrow ? inv2 : inv1);
                size_t off = (size_t)(b * CS + q0 + r1 + hrow * 8) * CD
                           + (size_t)h * CHD + cc;
                __nv_bfloat16 h0 = __float2bfloat16_rn(o0);
                __nv_bfloat16 h1 = __float2bfloat16_rn(o1);
                __nv_bfloat162 hv(h0, h1);
                __nv_bfloat162 lv(__float2bfloat16_rn(o0 - __bfloat162float(h0)),
                                  __float2bfloat16_rn(o1 - __bfloat162float(h1)));
                *(uint32_t*)(&g_aoh[off]) = *(uint32_t*)&hv;
                *(uint32_t*)(&g_aol[off]) = *(uint32_t*)&lv;
            }
        }
    }
}

// ---------------------------------------------------------------------------
extern "C" void kernel_launch(void* const* d_in, const int* in_sizes, int n_in,
                              void* d_out, int out_size)
{
    const float* X    = (const float*)d_in[0];
    const float* mask = (const float*)d_in[1];
    const float* Wq   = (const float*)d_in[2];
    const float* Wk   = (const float*)d_in[3];
    const float* Wv   = (const float*)d_in[4];
    const float* Wo   = (const float*)d_in[5];
    float* out = (float*)d_out;

    float *qp, *kp;
    cudaGetSymbolAddress((void**)&qp, g_q);
    cudaGetSymbolAddress((void**)&kp, g_k);
    __nv_bfloat16 *xh, *xl, *wqh, *wql, *wkh, *wkl, *wvh, *wvl, *woh, *wol, *aoh, *aol;
    __nv_bfloat16 *vh, *vl;
    cudaGetSymbolAddress((void**)&xh,  g_xh);
    cudaGetSymbolAddress((void**)&xl,  g_xl);
    cudaGetSymbolAddress((void**)&wqh, g_wqh);
    cudaGetSymbolAddress((void**)&wql, g_wql);
    cudaGetSymbolAddress((void**)&wkh, g_wkh);
    cudaGetSymbolAddress((void**)&wkl, g_wkl);
    cudaGetSymbolAddress((void**)&wvh, g_wvh);
    cudaGetSymbolAddress((void**)&wvl, g_wvl);
    cudaGetSymbolAddress((void**)&woh, g_woh);
    cudaGetSymbolAddress((void**)&wol, g_wol);
    cudaGetSymbolAddress((void**)&aoh, g_aoh);
    cudaGetSymbolAddress((void**)&aol, g_aol);
    cudaGetSymbolAddress((void**)&vh,  g_vh);
    cudaGetSymbolAddress((void**)&vl,  g_vl);

    cudaFuncSetAttribute(flash_mma, cudaFuncAttributeMaxDynamicSharedMemorySize,
                         FLASH_SMEM);
    cudaFuncSetAttribute(gemm_bf16x3, cudaFuncAttributeMaxDynamicSharedMemorySize,
                         GEMM_SMEM);

    init_invf<<<1, 64>>>();

    const int n4x = CM * CD / 4, n4w = CD * CD / 4;
    convert_hilo<<<n4x / 256, 256>>>(X,  xh,  xl,  n4x);
    convert_hilo<<<n4w / 256, 256>>>(Wq, wqh, wql, n4w);
    convert_hilo<<<n4w / 256, 256>>>(Wk, wkh, wkl, n4w);
    convert_hilo<<<n4w / 256, 256>>>(Wv, wvh, wvl, n4w);
    convert_hilo<<<n4w / 256, 256>>>(Wo, woh, wol, n4w);

    // fused Q/K/V projections; z==2 (V) writes bf16 hi/lo planes directly
    gemm_bf16x3<<<dim3(CD / 128, CM / 128, 3), 256, GEMM_SMEM>>>(
        xh, xl, wqh, wql, wkh, wkl, wvh, wvl, qp, kp, vh, vl, 2, CD, CD);

    rope_split<<<(CM * CH * 64) / 256, 256>>>();

    flash_mma<<<dim3(CS / 128, CH, CB), 256, FLASH_SMEM>>>(mask);

    // O projection (fp32 out)
    gemm_bf16x3<<<dim3(CD / 128, CM / 128, 1), 256, GEMM_SMEM>>>(
        aoh, aol, woh, wol, woh, wol, woh, wol, out, out, nullptr, nullptr, -1, CD, CD);
}